// round 11
// baseline (speedup 1.0000x reference)
#include <cuda_runtime.h>
#include <cuda_bf16.h>
#include <cstdint>

// ===================== problem constants =====================
#define N_TOK 8192
#define DIM   128
#define NB    136                 // 128 proj cols + 1 rowsum + 7 pad
#define KT    32                  // K elems per stage
#define NITER (N_TOK / KT)        // 256
#define ROWB  96                  // smem row stride bytes (64 B data + 32 pad), A and B alike
#define A_TILE_B (128 * ROWB)     // 12288 B (bf16)
#define B_TILE_B (NB * ROWB)      // 13056 B (bf16)
#define A_BASE 1024
#define B_BASE (A_BASE + 2 * A_TILE_B)          // 25600
#define SMEM_MAIN (B_BASE + 4 * B_TILE_B)       // 77824 B

// prep tiles (unchanged)
#define PROWF 72
#define PT_F  (128 * PROWF)
#define PREP_SMEM (4 * PT_F * 4)  // 147456 B
#define CT_ROW 133

// ===================== device scratch ==============
// g_B[p]: rows 0..127 = (h0 @ W[:, :128]^T)^T in bf16, row 128 = ones, 129..135 zero (.bss)
__device__ __nv_bfloat16 g_B[2][NB][N_TOK];
__device__ float g_S[2][N_TOK][DIM];   // self term h0 @ W[:,128:]^T (fp32-grade)

// ===================== helpers =====================
__device__ __forceinline__ uint32_t smem_u32(const void* p) {
    uint32_t a;
    asm("{ .reg .u64 t; cvta.to.shared.u64 t, %1; cvt.u32.u64 %0, t; }" : "=r"(a) : "l"(p));
    return a;
}
__device__ __forceinline__ float tf32rn(float x) {
    uint32_t v;
    asm("cvt.rn.tf32.f32 %0, %1;" : "=r"(v) : "f"(x));
    return __uint_as_float(v);
}
__device__ __forceinline__ uint32_t packbf(float hi, float lo) {   // {hi | lo} bf16x2
    uint32_t r;
    asm("cvt.rn.bf16x2.f32 %0, %1, %2;" : "=r"(r) : "f"(hi), "f"(lo));
    return r;
}

#define CP_ASYNC16(dst, src) \
    asm volatile("cp.async.cg.shared.global [%0], [%1], 16;" :: "r"(dst), "l"(src) : "memory")
#define CP_COMMIT() asm volatile("cp.async.commit_group;" ::: "memory")
#define CP_WAITG(n) asm volatile("cp.async.wait_group %0;" :: "n"(n) : "memory")

// m16n8k8 tf32 (prep)
__device__ __forceinline__ void mma_tf32(float* d, float a0, float a1, float a2, float a3,
                                         float b0, float b1) {
    asm volatile(
        "mma.sync.aligned.m16n8k8.row.col.f32.tf32.tf32.f32 "
        "{%0,%1,%2,%3}, {%4,%5,%6,%7}, {%8,%9}, {%0,%1,%2,%3};"
        : "+f"(d[0]), "+f"(d[1]), "+f"(d[2]), "+f"(d[3])
        : "r"(__float_as_uint(a0)), "r"(__float_as_uint(a1)),
          "r"(__float_as_uint(a2)), "r"(__float_as_uint(a3)),
          "r"(__float_as_uint(b0)), "r"(__float_as_uint(b1)));
}
// m16n8k16 bf16 (main)
__device__ __forceinline__ void mma_bf16(float* d, uint32_t a0, uint32_t a1, uint32_t a2,
                                         uint32_t a3, uint32_t b0, uint32_t b1) {
    asm volatile(
        "mma.sync.aligned.m16n8k16.row.col.f32.bf16.bf16.f32 "
        "{%0,%1,%2,%3}, {%4,%5,%6,%7}, {%8,%9}, {%0,%1,%2,%3};"
        : "+f"(d[0]), "+f"(d[1]), "+f"(d[2]), "+f"(d[3])
        : "r"(a0), "r"(a1), "r"(a2), "r"(a3), "r"(b0), "r"(b1));
}

// ===================== prep: tensor-core, 3-term tf32 split (fp32-grade) =====================
__global__ void __launch_bounds__(256, 1) prep_kernel(const float* __restrict__ h0,
                                                      const float* __restrict__ Wpos,
                                                      const float* __restrict__ Wneg) {
    extern __shared__ float psm[];
    float* Ahi = psm;
    float* Alo = psm + PT_F;
    float* Whi = psm + 2 * PT_F;
    float* Wlo = psm + 3 * PT_F;

    int mode = blockIdx.y;
    int p = mode >> 1, half = mode & 1;
    const float* W = p ? Wneg : Wpos;
    int m0 = blockIdx.x * 128;
    int t = threadIdx.x;
    int lane = t & 31, wid = t >> 5;
    int g = lane >> 2, t4 = lane & 3;
    int warp_r = wid & 3, warp_c = wid >> 2;

    float acc[2][8][4];
#pragma unroll
    for (int mt = 0; mt < 2; mt++)
#pragma unroll
        for (int nt = 0; nt < 8; nt++)
#pragma unroll
            for (int q = 0; q < 4; q++) acc[mt][nt][q] = 0.f;

    for (int kc = 0; kc < 2; kc++) {
        __syncthreads();
        for (int i = t; i < 2048; i += 256) {
            int r = i >> 4, c4 = i & 15;
            float4 v = *reinterpret_cast<const float4*>(h0 + (size_t)(m0 + r) * DIM + kc * 64 + c4 * 4);
            float4 hi, lo;
            hi.x = tf32rn(v.x); lo.x = tf32rn(v.x - hi.x);
            hi.y = tf32rn(v.y); lo.y = tf32rn(v.y - hi.y);
            hi.z = tf32rn(v.z); lo.z = tf32rn(v.z - hi.z);
            hi.w = tf32rn(v.w); lo.w = tf32rn(v.w - hi.w);
            *reinterpret_cast<float4*>(Ahi + r * PROWF + c4 * 4) = hi;
            *reinterpret_cast<float4*>(Alo + r * PROWF + c4 * 4) = lo;
        }
        for (int i = t; i < 2048; i += 256) {
            int r = i >> 4, c4 = i & 15;
            float4 v = *reinterpret_cast<const float4*>(W + (size_t)r * 256 + half * 128 + kc * 64 + c4 * 4);
            float4 hi, lo;
            hi.x = tf32rn(v.x); lo.x = tf32rn(v.x - hi.x);
            hi.y = tf32rn(v.y); lo.y = tf32rn(v.y - hi.y);
            hi.z = tf32rn(v.z); lo.z = tf32rn(v.z - hi.z);
            hi.w = tf32rn(v.w); lo.w = tf32rn(v.w - hi.w);
            *reinterpret_cast<float4*>(Whi + r * PROWF + c4 * 4) = hi;
            *reinterpret_cast<float4*>(Wlo + r * PROWF + c4 * 4) = lo;
        }
        __syncthreads();

        const float2* Ah2 = reinterpret_cast<const float2*>(Ahi);
        const float2* Al2 = reinterpret_cast<const float2*>(Alo);
        const float2* Wh2 = reinterpret_cast<const float2*>(Whi);
        const float2* Wl2 = reinterpret_cast<const float2*>(Wlo);
        int arow = 32 * warp_r + g;
        int brow = 64 * warp_c + g;
#pragma unroll
        for (int kk = 0; kk < 8; kk++) {
            float2 ah0[2], ah1[2], al0[2], al1[2];
#pragma unroll
            for (int mt = 0; mt < 2; mt++) {
                int r = arow + 16 * mt;
                ah0[mt] = Ah2[r * 36 + 4 * kk + t4];
                ah1[mt] = Ah2[(r + 8) * 36 + 4 * kk + t4];
                al0[mt] = Al2[r * 36 + 4 * kk + t4];
                al1[mt] = Al2[(r + 8) * 36 + 4 * kk + t4];
            }
            float2 bh[8], bl[8];
#pragma unroll
            for (int nt = 0; nt < 8; nt++) {
                int n = brow + 8 * nt;
                bh[nt] = Wh2[n * 36 + 4 * kk + t4];
                bl[nt] = Wl2[n * 36 + 4 * kk + t4];
            }
#pragma unroll
            for (int mt = 0; mt < 2; mt++)
#pragma unroll
                for (int nt = 0; nt < 8; nt++) {
                    mma_tf32(acc[mt][nt], ah0[mt].x, ah1[mt].x, ah0[mt].y, ah1[mt].y, bh[nt].x, bh[nt].y);
                    mma_tf32(acc[mt][nt], ah0[mt].x, ah1[mt].x, ah0[mt].y, ah1[mt].y, bl[nt].x, bl[nt].y);
                    mma_tf32(acc[mt][nt], al0[mt].x, al1[mt].x, al0[mt].y, al1[mt].y, bh[nt].x, bh[nt].y);
                }
        }
    }
    __syncthreads();

    float* Ct = psm;
#pragma unroll
    for (int mt = 0; mt < 2; mt++) {
        int row = 32 * warp_r + 16 * mt + g;
#pragma unroll
        for (int nt = 0; nt < 8; nt++) {
            int col = 64 * warp_c + 8 * nt + 2 * t4;
            Ct[row * CT_ROW + col]           = acc[mt][nt][0];
            Ct[row * CT_ROW + col + 1]       = acc[mt][nt][1];
            Ct[(row + 8) * CT_ROW + col]     = acc[mt][nt][2];
            Ct[(row + 8) * CT_ROW + col + 1] = acc[mt][nt][3];
        }
    }
    __syncthreads();

    if (half == 0) {
        for (int i = t; i < 16384; i += 256) {          // n-major, m contiguous -> coalesced
            int n = i >> 7, m = i & 127;
            g_B[p][n][m0 + m] = __float2bfloat16(Ct[m * CT_ROW + n]);
        }
    } else {
        for (int i = t; i < 16384; i += 256) {
            int m = i >> 7, n = i & 127;
            g_S[p][m0 + m][n] = Ct[m * CT_ROW + n];
        }
    }
}

__global__ void ones_kernel() {
    int i = blockIdx.x * 256 + threadIdx.x;   // 2 * 8192 elems
    int p = i >> 13, k = i & (N_TOK - 1);
    g_B[p][DIM][k] = __float2bfloat16(1.0f);
}

// ===================== main: C = adj_p[m-tile] @ B_p^T, bf16 m16n8k16 ========================
// grid (64, 2). 8 warps: warp_r = wid&3, warp_c = wid>>2 (9 / 8 n-tiles; col 128 = rowsum).
// A path: LDG.128 fp32 (stage it+2) -> regs -> cvt bf16 -> STS.64 (stage it+1) -> LDS.64 frags.
// B path: cp.async 4-deep (bf16 from g_B). One __syncthreads per stage guards both.
__global__ void __launch_bounds__(256, 1) main_kernel(const float* __restrict__ adj_pos,
                                                      const float* __restrict__ adj_neg,
                                                      float* __restrict__ out) {
    extern __shared__ char smc[];
    float* sums = reinterpret_cast<float*>(smc);          // [128]
    uint32_t sb = smem_u32(smc);

    int tid = threadIdx.x;
    int lane = tid & 31, wid = tid >> 5;
    int g = lane >> 2, t4 = lane & 3;
    int warp_r = wid & 3, warp_c = wid >> 2;
    const int NT = warp_c ? 8 : 9;
    int m0 = blockIdx.x * 128;
    int p = blockIdx.y;
    const float* Ag = p ? adj_neg : adj_pos;
    const __nv_bfloat16* Bg = &g_B[p][0][0];

    // B stage loader (cp.async, commits one group)
    auto load_B = [&](int it, int s) {
        int k0 = it * KT;
        uint32_t bbuf = sb + B_BASE + (uint32_t)s * B_TILE_B;
#pragma unroll
        for (int i = tid; i < 544; i += 256) {            // 136 rows x 4 x 16B
            int r = i >> 2, c = i & 3;
            CP_ASYNC16(bbuf + (uint32_t)(r * ROWB + c * 16),
                       Bg + (size_t)r * N_TOK + k0 + c * 8);
        }
        CP_COMMIT();
    };
    // A LDG: 4 float4 per thread, rows r = idx>>3, cols c = idx&7 (16B each)
    float4 ap[4];
    auto ldg_A = [&](int it) {
        int k0 = it * KT;
#pragma unroll
        for (int j = 0; j < 4; j++) {
            int idx = tid + 256 * j;
            int r = idx >> 3, c = idx & 7;
            ap[j] = *reinterpret_cast<const float4*>(Ag + (size_t)(m0 + r) * N_TOK + k0 + c * 4);
        }
    };
    // A STS: convert held regs to bf16, store 8 B per slot
    auto sts_A = [&](int it) {
        uint32_t abuf = sb + A_BASE + (uint32_t)(it & 1) * A_TILE_B;
#pragma unroll
        for (int j = 0; j < 4; j++) {
            int idx = tid + 256 * j;
            int r = idx >> 3, c = idx & 7;
            uint2 u;
            u.x = packbf(ap[j].y, ap[j].x);   // k even pair (lo = first k)
            u.y = packbf(ap[j].w, ap[j].z);
            *reinterpret_cast<uint2*>(smc + A_BASE + (it & 1) * A_TILE_B + r * ROWB + c * 8) = u;
            (void)abuf;
        }
    };

    float acc[2][9][4];
#pragma unroll
    for (int mt = 0; mt < 2; mt++)
#pragma unroll
        for (int nt = 0; nt < 9; nt++)
#pragma unroll
            for (int q = 0; q < 4; q++) acc[mt][nt][q] = 0.f;

    int arow = 32 * warp_r + g;
    int brow = (warp_c ? 72 : 0) + g;

    // ---- prologue: B(0..2) async; A(0) ldg->sts; A(1) ldg->regs ----
    load_B(0, 0); load_B(1, 1); load_B(2, 2);
    ldg_A(0);
    sts_A(0);
    ldg_A(1);

    for (int it = 0; it < NITER; it++) {
        int s = it & 3;
        CP_WAITG(2);            // B(it) arrived (B(it+1), B(it+2) pending)
        __syncthreads();        // publishes STS A(it); prior-stage buffers released

        if (it + 1 < NITER) sts_A(it + 1);          // from ap (loaded at it-1)
        if (it + 2 < NITER) { ldg_A(it + 2); load_B(it + 2, (it + 2) & 3); }
        else CP_COMMIT();                            // keep group count uniform

        const uint2* Aw = reinterpret_cast<const uint2*>(smc + A_BASE + (it & 1) * A_TILE_B);
        const uint2* Bw = reinterpret_cast<const uint2*>(smc + B_BASE + (size_t)s * B_TILE_B);
#pragma unroll
        for (int kk = 0; kk < 2; kk++) {
            uint2 a0[2], a1[2];
#pragma unroll
            for (int mt = 0; mt < 2; mt++) {
                int r = arow + 16 * mt;
                a0[mt] = Aw[r * 12 + 4 * kk + t4];        // (g,   k 16kk+4t4 .. +3)
                a1[mt] = Aw[(r + 8) * 12 + 4 * kk + t4];  // (g+8)
            }
            uint2 bf[9];
#pragma unroll
            for (int nt = 0; nt < 9; nt++)
                if (nt < NT) bf[nt] = Bw[(brow + 8 * nt) * 12 + 4 * kk + t4];
#pragma unroll
            for (int mt = 0; mt < 2; mt++)
#pragma unroll
                for (int nt = 0; nt < 9; nt++)
                    if (nt < NT)
                        mma_bf16(acc[mt][nt], a0[mt].x, a1[mt].x, a0[mt].y, a1[mt].y,
                                 bf[nt].x, bf[nt].y);
        }
    }

    // ---- epilogue ----
    __syncthreads();
    // rowsum = global col 128 = warp_c==1, nt==7, 2t4==0
    if (warp_c == 1 && t4 == 0) {
#pragma unroll
        for (int mt = 0; mt < 2; mt++) {
            int row = 32 * warp_r + 16 * mt + g;
            sums[row]     = acc[mt][7][0];
            sums[row + 8] = acc[mt][7][2];
        }
    }
    __syncthreads();

    int cbase = warp_c ? 72 : 0;
#pragma unroll
    for (int mt = 0; mt < 2; mt++) {
        int row = 32 * warp_r + 16 * mt + g;
        float invA = 1.0f / sums[row];
        float invB = 1.0f / sums[row + 8];
        int mA = m0 + row, mB = mA + 8;
        const float* SA = &g_S[p][mA][0];
        const float* SB = &g_S[p][mB][0];
        float* oA = out + (size_t)mA * 256 + p;
        float* oB = out + (size_t)mB * 256 + p;
#pragma unroll
        for (int nt = 0; nt < 9; nt++) {
            int col = cbase + 8 * nt + 2 * t4;
            if (nt < NT && col < DIM) {
                float2 sA = *reinterpret_cast<const float2*>(SA + col);
                float2 sB = *reinterpret_cast<const float2*>(SB + col);
                oA[(size_t)(col + 0) * 2] = fmaxf(fmaf(acc[mt][nt][0], invA, sA.x), 0.f);
                oA[(size_t)(col + 1) * 2] = fmaxf(fmaf(acc[mt][nt][1], invA, sA.y), 0.f);
                oB[(size_t)(col + 0) * 2] = fmaxf(fmaf(acc[mt][nt][2], invB, sB.x), 0.f);
                oB[(size_t)(col + 1) * 2] = fmaxf(fmaf(acc[mt][nt][3], invB, sB.y), 0.f);
            }
        }
    }
}

// ===================== host =====================
extern "C" void kernel_launch(void* const* d_in, const int* in_sizes, int n_in,
                              void* d_out, int out_size) {
    // metadata order: inputs, adj_pos, adj_neg, h0, WB0, WU0, start, end
    const float* adj_pos = (const float*)d_in[1];
    const float* adj_neg = (const float*)d_in[2];
    const float* h0      = (const float*)d_in[3];
    const float* WB0     = (const float*)d_in[4];
    const float* WU0     = (const float*)d_in[5];
    float* out = (float*)d_out;

    cudaFuncSetAttribute(prep_kernel, cudaFuncAttributeMaxDynamicSharedMemorySize, PREP_SMEM);
    cudaFuncSetAttribute(main_kernel, cudaFuncAttributeMaxDynamicSharedMemorySize, SMEM_MAIN);

    prep_kernel<<<dim3(64, 4), 256, PREP_SMEM>>>(h0, WB0, WU0);
    ones_kernel<<<64, 256>>>();
    main_kernel<<<dim3(64, 2), 256, SMEM_MAIN>>>(adj_pos, adj_neg, out);
}

// round 13
// speedup vs baseline: 1.2850x; 1.2850x over previous
#include <cuda_runtime.h>
#include <cuda_bf16.h>
#include <cstdint>

// ===================== problem constants =====================
#define N_TOK 8192
#define DIM   128
#define NB    136                 // 128 proj cols + 1 rowsum + 7 pad
#define KT    64                  // K elems per stage
#define NITER (N_TOK / KT)        // 128
#define AROWB 320                 // A smem row bytes: 64 f32 = 256 B data + 64 pad (stride4=20)
#define BROWB 160                 // B smem row bytes: 64 bf16 = 128 B data + 32 pad (stride2=20)
#define A_TILE_B (128 * AROWB)    // 40960 B
#define B_TILE_B (NB * BROWB)     // 21760 B
#define STAGE_B  (A_TILE_B + B_TILE_B)   // 62720 B
#define SMEM_MAIN (1024 + 3 * STAGE_B)   // 189184 B

// prep tiles
#define PROWF 72
#define PT_F  (128 * PROWF)
#define PREP_SMEM (4 * PT_F * 4)  // 147456 B
#define CT_ROW 133

// ===================== device scratch ==============
// g_B[p]: rows 0..127 = (h0 @ W[:, :128]^T)^T in bf16, row 128 = ones, 129..135 zero (.bss)
__device__ __nv_bfloat16 g_B[2][NB][N_TOK];
__device__ float g_S[2][N_TOK][DIM];   // self term h0 @ W[:,128:]^T (fp32-grade)

// ===================== helpers =====================
__device__ __forceinline__ uint32_t smem_u32(const void* p) {
    uint32_t a;
    asm("{ .reg .u64 t; cvta.to.shared.u64 t, %1; cvt.u32.u64 %0, t; }" : "=r"(a) : "l"(p));
    return a;
}
__device__ __forceinline__ float tf32rn(float x) {
    uint32_t v;
    asm("cvt.rn.tf32.f32 %0, %1;" : "=r"(v) : "f"(x));
    return __uint_as_float(v);
}
__device__ __forceinline__ uint32_t packbf(float hi, float lo) {   // {hi | lo} bf16x2
    uint32_t r;
    asm("cvt.rn.bf16x2.f32 %0, %1, %2;" : "=r"(r) : "f"(hi), "f"(lo));
    return r;
}

#define CP_ASYNC16(dst, src) \
    asm volatile("cp.async.cg.shared.global [%0], [%1], 16;" :: "r"(dst), "l"(src) : "memory")
#define CP_COMMIT() asm volatile("cp.async.commit_group;" ::: "memory")
#define CP_WAITG(n) asm volatile("cp.async.wait_group %0;" :: "n"(n) : "memory")

// m16n8k8 tf32 (prep)
__device__ __forceinline__ void mma_tf32(float* d, float a0, float a1, float a2, float a3,
                                         float b0, float b1) {
    asm volatile(
        "mma.sync.aligned.m16n8k8.row.col.f32.tf32.tf32.f32 "
        "{%0,%1,%2,%3}, {%4,%5,%6,%7}, {%8,%9}, {%0,%1,%2,%3};"
        : "+f"(d[0]), "+f"(d[1]), "+f"(d[2]), "+f"(d[3])
        : "r"(__float_as_uint(a0)), "r"(__float_as_uint(a1)),
          "r"(__float_as_uint(a2)), "r"(__float_as_uint(a3)),
          "r"(__float_as_uint(b0)), "r"(__float_as_uint(b1)));
}
// m16n8k16 bf16 (main)
__device__ __forceinline__ void mma_bf16(float* d, uint32_t a0, uint32_t a1, uint32_t a2,
                                         uint32_t a3, uint32_t b0, uint32_t b1) {
    asm volatile(
        "mma.sync.aligned.m16n8k16.row.col.f32.bf16.bf16.f32 "
        "{%0,%1,%2,%3}, {%4,%5,%6,%7}, {%8,%9}, {%0,%1,%2,%3};"
        : "+f"(d[0]), "+f"(d[1]), "+f"(d[2]), "+f"(d[3])
        : "r"(a0), "r"(a1), "r"(a2), "r"(a3), "r"(b0), "r"(b1));
}

// ===================== prep: tensor-core, 3-term tf32 split (fp32-grade) =====================
__global__ void __launch_bounds__(256, 1) prep_kernel(const float* __restrict__ h0,
                                                      const float* __restrict__ Wpos,
                                                      const float* __restrict__ Wneg) {
    extern __shared__ float psm[];
    float* Ahi = psm;
    float* Alo = psm + PT_F;
    float* Whi = psm + 2 * PT_F;
    float* Wlo = psm + 3 * PT_F;

    int mode = blockIdx.y;
    int p = mode >> 1, half = mode & 1;
    const float* W = p ? Wneg : Wpos;
    int m0 = blockIdx.x * 128;
    int t = threadIdx.x;
    int lane = t & 31, wid = t >> 5;
    int g = lane >> 2, t4 = lane & 3;
    int warp_r = wid & 3, warp_c = wid >> 2;

    float acc[2][8][4];
#pragma unroll
    for (int mt = 0; mt < 2; mt++)
#pragma unroll
        for (int nt = 0; nt < 8; nt++)
#pragma unroll
            for (int q = 0; q < 4; q++) acc[mt][nt][q] = 0.f;

    for (int kc = 0; kc < 2; kc++) {
        __syncthreads();
        for (int i = t; i < 2048; i += 256) {
            int r = i >> 4, c4 = i & 15;
            float4 v = *reinterpret_cast<const float4*>(h0 + (size_t)(m0 + r) * DIM + kc * 64 + c4 * 4);
            float4 hi, lo;
            hi.x = tf32rn(v.x); lo.x = tf32rn(v.x - hi.x);
            hi.y = tf32rn(v.y); lo.y = tf32rn(v.y - hi.y);
            hi.z = tf32rn(v.z); lo.z = tf32rn(v.z - hi.z);
            hi.w = tf32rn(v.w); lo.w = tf32rn(v.w - hi.w);
            *reinterpret_cast<float4*>(Ahi + r * PROWF + c4 * 4) = hi;
            *reinterpret_cast<float4*>(Alo + r * PROWF + c4 * 4) = lo;
        }
        for (int i = t; i < 2048; i += 256) {
            int r = i >> 4, c4 = i & 15;
            float4 v = *reinterpret_cast<const float4*>(W + (size_t)r * 256 + half * 128 + kc * 64 + c4 * 4);
            float4 hi, lo;
            hi.x = tf32rn(v.x); lo.x = tf32rn(v.x - hi.x);
            hi.y = tf32rn(v.y); lo.y = tf32rn(v.y - hi.y);
            hi.z = tf32rn(v.z); lo.z = tf32rn(v.z - hi.z);
            hi.w = tf32rn(v.w); lo.w = tf32rn(v.w - hi.w);
            *reinterpret_cast<float4*>(Whi + r * PROWF + c4 * 4) = hi;
            *reinterpret_cast<float4*>(Wlo + r * PROWF + c4 * 4) = lo;
        }
        __syncthreads();

        const float2* Ah2 = reinterpret_cast<const float2*>(Ahi);
        const float2* Al2 = reinterpret_cast<const float2*>(Alo);
        const float2* Wh2 = reinterpret_cast<const float2*>(Whi);
        const float2* Wl2 = reinterpret_cast<const float2*>(Wlo);
        int arow = 32 * warp_r + g;
        int brow = 64 * warp_c + g;
#pragma unroll
        for (int kk = 0; kk < 8; kk++) {
            float2 ah0[2], ah1[2], al0[2], al1[2];
#pragma unroll
            for (int mt = 0; mt < 2; mt++) {
                int r = arow + 16 * mt;
                ah0[mt] = Ah2[r * 36 + 4 * kk + t4];
                ah1[mt] = Ah2[(r + 8) * 36 + 4 * kk + t4];
                al0[mt] = Al2[r * 36 + 4 * kk + t4];
                al1[mt] = Al2[(r + 8) * 36 + 4 * kk + t4];
            }
            float2 bh[8], bl[8];
#pragma unroll
            for (int nt = 0; nt < 8; nt++) {
                int n = brow + 8 * nt;
                bh[nt] = Wh2[n * 36 + 4 * kk + t4];
                bl[nt] = Wl2[n * 36 + 4 * kk + t4];
            }
#pragma unroll
            for (int mt = 0; mt < 2; mt++)
#pragma unroll
                for (int nt = 0; nt < 8; nt++) {
                    mma_tf32(acc[mt][nt], ah0[mt].x, ah1[mt].x, ah0[mt].y, ah1[mt].y, bh[nt].x, bh[nt].y);
                    mma_tf32(acc[mt][nt], ah0[mt].x, ah1[mt].x, ah0[mt].y, ah1[mt].y, bl[nt].x, bl[nt].y);
                    mma_tf32(acc[mt][nt], al0[mt].x, al1[mt].x, al0[mt].y, al1[mt].y, bh[nt].x, bh[nt].y);
                }
        }
    }
    __syncthreads();

    float* Ct = psm;
#pragma unroll
    for (int mt = 0; mt < 2; mt++) {
        int row = 32 * warp_r + 16 * mt + g;
#pragma unroll
        for (int nt = 0; nt < 8; nt++) {
            int col = 64 * warp_c + 8 * nt + 2 * t4;
            Ct[row * CT_ROW + col]           = acc[mt][nt][0];
            Ct[row * CT_ROW + col + 1]       = acc[mt][nt][1];
            Ct[(row + 8) * CT_ROW + col]     = acc[mt][nt][2];
            Ct[(row + 8) * CT_ROW + col + 1] = acc[mt][nt][3];
        }
    }
    __syncthreads();

    if (half == 0) {
        for (int i = t; i < 16384; i += 256) {          // n-major, m contiguous -> coalesced
            int n = i >> 7, m = i & 127;
            g_B[p][n][m0 + m] = __float2bfloat16(Ct[m * CT_ROW + n]);
        }
        for (int i = t; i < 128; i += 256)              // ones row slice (replaces ones_kernel)
            g_B[p][DIM][m0 + i] = __float2bfloat16(1.0f);
    } else {
        for (int i = t; i < 16384; i += 256) {
            int m = i >> 7, n = i & 127;
            g_S[p][m0 + m][n] = Ct[m * CT_ROW + n];
        }
    }
}

// ===================== main: C = adj_p[m-tile] @ B_p^T, bf16 m16n8k16, KT=64 =================
// grid (64, 2). 8 warps: warp_r = wid&3, warp_c = wid>>2 (9 / 8 n-tiles; col 128 = rowsum).
// A: cp.async fp32, row 320 B (stride4=20, conflict-free with t4 low bits). Frag = LDS.128,
//    cvt to bf16x2 in regs (k-relabel: HW k-slots <-> global k 16kk+4t4..+3 on both operands).
// B: cp.async bf16 from g_B, row 160 B (uint2 stride 20, conflict-free). Frag = LDS.64.
// 3 buffers, waitg(2) + 2 syncs per 64-K stage.
__global__ void __launch_bounds__(256, 1) main_kernel(const float* __restrict__ adj_pos,
                                                      const float* __restrict__ adj_neg,
                                                      float* __restrict__ out) {
    extern __shared__ char smc[];
    float* sums = reinterpret_cast<float*>(smc);          // [128]
    uint32_t sb = smem_u32(smc);

    int tid = threadIdx.x;
    int lane = tid & 31, wid = tid >> 5;
    int g = lane >> 2, t4 = lane & 3;
    int warp_r = wid & 3, warp_c = wid >> 2;
    const int NT = warp_c ? 8 : 9;
    int m0 = blockIdx.x * 128;
    int p = blockIdx.y;
    const float* Ag = p ? adj_neg : adj_pos;
    const __nv_bfloat16* Bg = &g_B[p][0][0];

    auto load_stage = [&](int it, int s) {
        int k0 = it * KT;
        uint32_t abuf = sb + 1024 + (uint32_t)s * STAGE_B;
        uint32_t bbuf = abuf + A_TILE_B;
#pragma unroll
        for (int i = tid; i < 2048; i += 256) {           // A: 128 rows x 16 x 16B (f32)
            int r = i >> 4, c = i & 15;
            CP_ASYNC16(abuf + (uint32_t)(r * AROWB + c * 16),
                       Ag + (size_t)(m0 + r) * N_TOK + k0 + c * 4);
        }
#pragma unroll
        for (int i = tid; i < 1088; i += 256) {           // B: 136 rows x 8 x 16B (bf16)
            int r = i >> 3, c = i & 7;
            CP_ASYNC16(bbuf + (uint32_t)(r * BROWB + c * 16),
                       Bg + (size_t)r * N_TOK + k0 + c * 8);
        }
        CP_COMMIT();
    };

    float acc[2][9][4];
#pragma unroll
    for (int mt = 0; mt < 2; mt++)
#pragma unroll
        for (int nt = 0; nt < 9; nt++)
#pragma unroll
            for (int q = 0; q < 4; q++) acc[mt][nt][q] = 0.f;

    int arow = 32 * warp_r + g;
    int brow = (warp_c ? 72 : 0) + g;

    // prologue: 3 stages in flight
    load_stage(0, 0); load_stage(1, 1); load_stage(2, 2);

    for (int it = 0; it < NITER; it++) {
        int s = it - (it / 3) * 3;          // it % 3
        CP_WAITG(2);            // stage `it` complete (it+1, it+2 pending)
        __syncthreads();        // all threads see stage `it`

        const float4* As4 = reinterpret_cast<const float4*>(smc + 1024 + (size_t)s * STAGE_B);
        const uint2* Bw = reinterpret_cast<const uint2*>(smc + 1024 + (size_t)s * STAGE_B + A_TILE_B);
#pragma unroll
        for (int kk = 0; kk < 4; kk++) {
            // A frags: float4 at (row, global k 16kk+4t4), 20 float4s per row
            uint32_t a[2][4];
#pragma unroll
            for (int mt = 0; mt < 2; mt++) {
                int r = arow + 16 * mt;
                float4 v0 = As4[r * 20 + 4 * kk + t4];
                float4 v1 = As4[(r + 8) * 20 + 4 * kk + t4];
                a[mt][0] = packbf(v0.y, v0.x);   // (g,   k0 k1)
                a[mt][1] = packbf(v1.y, v1.x);   // (g+8, k0 k1)
                a[mt][2] = packbf(v0.w, v0.z);   // (g,   k2 k3)
                a[mt][3] = packbf(v1.w, v1.z);   // (g+8, k2 k3)
            }
            uint2 bf[9];
#pragma unroll
            for (int nt = 0; nt < 9; nt++)
                if (nt < NT) bf[nt] = Bw[(brow + 8 * nt) * 20 + 4 * kk + t4];
#pragma unroll
            for (int mt = 0; mt < 2; mt++)
#pragma unroll
                for (int nt = 0; nt < 9; nt++)
                    if (nt < NT)
                        mma_bf16(acc[mt][nt], a[mt][0], a[mt][1], a[mt][2], a[mt][3],
                                 bf[nt].x, bf[nt].y);
        }

        __syncthreads();        // buffer s fully consumed by all warps
        int nit = it + 3;
        if (nit < NITER) load_stage(nit, s);
        else CP_COMMIT();       // keep group count uniform (empty group)
    }

    // ---- epilogue ----
    // rowsum = global col 128 = warp_c==1, nt==7, 2t4==0
    if (warp_c == 1 && t4 == 0) {
#pragma unroll
        for (int mt = 0; mt < 2; mt++) {
            int row = 32 * warp_r + 16 * mt + g;
            sums[row]     = acc[mt][7][0];
            sums[row + 8] = acc[mt][7][2];
        }
    }
    __syncthreads();

    int cbase = warp_c ? 72 : 0;
#pragma unroll
    for (int mt = 0; mt < 2; mt++) {
        int row = 32 * warp_r + 16 * mt + g;
        float invA = 1.0f / sums[row];
        float invB = 1.0f / sums[row + 8];
        int mA = m0 + row, mB = mA + 8;
        const float* SA = &g_S[p][mA][0];
        const float* SB = &g_S[p][mB][0];
        float* oA = out + (size_t)mA * 256 + p;
        float* oB = out + (size_t)mB * 256 + p;
#pragma unroll
        for (int nt = 0; nt < 9; nt++) {
            int col = cbase + 8 * nt + 2 * t4;
            if (nt < NT && col < DIM) {
                float2 sA = *reinterpret_cast<const float2*>(SA + col);
                float2 sB = *reinterpret_cast<const float2*>(SB + col);
                oA[(size_t)(col + 0) * 2] = fmaxf(fmaf(acc[mt][nt][0], invA, sA.x), 0.f);
                oA[(size_t)(col + 1) * 2] = fmaxf(fmaf(acc[mt][nt][1], invA, sA.y), 0.f);
                oB[(size_t)(col + 0) * 2] = fmaxf(fmaf(acc[mt][nt][2], invB, sB.x), 0.f);
                oB[(size_t)(col + 1) * 2] = fmaxf(fmaf(acc[mt][nt][3], invB, sB.y), 0.f);
            }
        }
    }
}

// ===================== host =====================
extern "C" void kernel_launch(void* const* d_in, const int* in_sizes, int n_in,
                              void* d_out, int out_size) {
    // metadata order: inputs, adj_pos, adj_neg, h0, WB0, WU0, start, end
    const float* adj_pos = (const float*)d_in[1];
    const float* adj_neg = (const float*)d_in[2];
    const float* h0      = (const float*)d_in[3];
    const float* WB0     = (const float*)d_in[4];
    const float* WU0     = (const float*)d_in[5];
    float* out = (float*)d_out;

    cudaFuncSetAttribute(prep_kernel, cudaFuncAttributeMaxDynamicSharedMemorySize, PREP_SMEM);
    cudaFuncSetAttribute(main_kernel, cudaFuncAttributeMaxDynamicSharedMemorySize, SMEM_MAIN);

    prep_kernel<<<dim3(64, 4), 256, PREP_SMEM>>>(h0, WB0, WU0);
    main_kernel<<<dim3(64, 2), 256, SMEM_MAIN>>>(adj_pos, adj_neg, out);
}

// round 15
// speedup vs baseline: 1.2998x; 1.0115x over previous
#include <cuda_runtime.h>
#include <cuda_bf16.h>
#include <cstdint>

// ===================== problem constants =====================
#define N_TOK 8192
#define DIM   128
#define KT    64                  // K elems per stage
#define NITER (N_TOK / KT)        // 128
#define AROWB 320                 // A smem row bytes: 64 f32 + 64 pad (float4 stride 20)
#define BROWB 160                 // B smem row bytes: 64 bf16 + 32 pad (uint2 stride 20)
#define A_TILE_B (128 * AROWB)    // 40960 B
#define B_TILE_B (128 * BROWB)    // 20480 B
#define STAGE_B  (A_TILE_B + B_TILE_B)   // 61440 B
#define SMEM_MAIN (1024 + 3 * STAGE_B)   // 185344 B

// prep tiles
#define PROWF 72
#define PT_F  (128 * PROWF)
#define PREP_SMEM (4 * PT_F * 4)  // 147456 B
#define CT_ROW 133

// ===================== device scratch ==============
// g_B[p][n][k] = bf16 of (h0 @ W[:, :128]^T)^T   (no ones row anymore)
__device__ __nv_bfloat16 g_B[2][DIM][N_TOK];
__device__ float g_S[2][N_TOK][DIM];   // self term h0 @ W[:,128:]^T (fp32-grade)

// ===================== helpers =====================
__device__ __forceinline__ uint32_t smem_u32(const void* p) {
    uint32_t a;
    asm("{ .reg .u64 t; cvta.to.shared.u64 t, %1; cvt.u32.u64 %0, t; }" : "=r"(a) : "l"(p));
    return a;
}
__device__ __forceinline__ float tf32rn(float x) {
    uint32_t v;
    asm("cvt.rn.tf32.f32 %0, %1;" : "=r"(v) : "f"(x));
    return __uint_as_float(v);
}
__device__ __forceinline__ uint32_t packbf(float hi, float lo) {   // {hi | lo} bf16x2
    uint32_t r;
    asm("cvt.rn.bf16x2.f32 %0, %1, %2;" : "=r"(r) : "f"(hi), "f"(lo));
    return r;
}

#define CP_ASYNC16(dst, src) \
    asm volatile("cp.async.cg.shared.global [%0], [%1], 16;" :: "r"(dst), "l"(src) : "memory")
#define CP_COMMIT() asm volatile("cp.async.commit_group;" ::: "memory")
#define CP_WAITG(n) asm volatile("cp.async.wait_group %0;" :: "n"(n) : "memory")

// m16n8k8 tf32 (prep)
__device__ __forceinline__ void mma_tf32(float* d, float a0, float a1, float a2, float a3,
                                         float b0, float b1) {
    asm volatile(
        "mma.sync.aligned.m16n8k8.row.col.f32.tf32.tf32.f32 "
        "{%0,%1,%2,%3}, {%4,%5,%6,%7}, {%8,%9}, {%0,%1,%2,%3};"
        : "+f"(d[0]), "+f"(d[1]), "+f"(d[2]), "+f"(d[3])
        : "r"(__float_as_uint(a0)), "r"(__float_as_uint(a1)),
          "r"(__float_as_uint(a2)), "r"(__float_as_uint(a3)),
          "r"(__float_as_uint(b0)), "r"(__float_as_uint(b1)));
}
// m16n8k16 bf16 (main)
__device__ __forceinline__ void mma_bf16(float* d, uint32_t a0, uint32_t a1, uint32_t a2,
                                         uint32_t a3, uint32_t b0, uint32_t b1) {
    asm volatile(
        "mma.sync.aligned.m16n8k16.row.col.f32.bf16.bf16.f32 "
        "{%0,%1,%2,%3}, {%4,%5,%6,%7}, {%8,%9}, {%0,%1,%2,%3};"
        : "+f"(d[0]), "+f"(d[1]), "+f"(d[2]), "+f"(d[3])
        : "r"(a0), "r"(a1), "r"(a2), "r"(a3), "r"(b0), "r"(b1));
}

// ===================== prep: tensor-core, 3-term tf32 split (fp32-grade) =====================
__global__ void __launch_bounds__(256, 1) prep_kernel(const float* __restrict__ h0,
                                                      const float* __restrict__ Wpos,
                                                      const float* __restrict__ Wneg) {
    extern __shared__ float psm[];
    float* Ahi = psm;
    float* Alo = psm + PT_F;
    float* Whi = psm + 2 * PT_F;
    float* Wlo = psm + 3 * PT_F;

    int mode = blockIdx.y;
    int p = mode >> 1, half = mode & 1;
    const float* W = p ? Wneg : Wpos;
    int m0 = blockIdx.x * 128;
    int t = threadIdx.x;
    int lane = t & 31, wid = t >> 5;
    int g = lane >> 2, t4 = lane & 3;
    int warp_r = wid & 3, warp_c = wid >> 2;

    float acc[2][8][4];
#pragma unroll
    for (int mt = 0; mt < 2; mt++)
#pragma unroll
        for (int nt = 0; nt < 8; nt++)
#pragma unroll
            for (int q = 0; q < 4; q++) acc[mt][nt][q] = 0.f;

    for (int kc = 0; kc < 2; kc++) {
        __syncthreads();
        for (int i = t; i < 2048; i += 256) {
            int r = i >> 4, c4 = i & 15;
            float4 v = *reinterpret_cast<const float4*>(h0 + (size_t)(m0 + r) * DIM + kc * 64 + c4 * 4);
            float4 hi, lo;
            hi.x = tf32rn(v.x); lo.x = tf32rn(v.x - hi.x);
            hi.y = tf32rn(v.y); lo.y = tf32rn(v.y - hi.y);
            hi.z = tf32rn(v.z); lo.z = tf32rn(v.z - hi.z);
            hi.w = tf32rn(v.w); lo.w = tf32rn(v.w - hi.w);
            *reinterpret_cast<float4*>(Ahi + r * PROWF + c4 * 4) = hi;
            *reinterpret_cast<float4*>(Alo + r * PROWF + c4 * 4) = lo;
        }
        for (int i = t; i < 2048; i += 256) {
            int r = i >> 4, c4 = i & 15;
            float4 v = *reinterpret_cast<const float4*>(W + (size_t)r * 256 + half * 128 + kc * 64 + c4 * 4);
            float4 hi, lo;
            hi.x = tf32rn(v.x); lo.x = tf32rn(v.x - hi.x);
            hi.y = tf32rn(v.y); lo.y = tf32rn(v.y - hi.y);
            hi.z = tf32rn(v.z); lo.z = tf32rn(v.z - hi.z);
            hi.w = tf32rn(v.w); lo.w = tf32rn(v.w - hi.w);
            *reinterpret_cast<float4*>(Whi + r * PROWF + c4 * 4) = hi;
            *reinterpret_cast<float4*>(Wlo + r * PROWF + c4 * 4) = lo;
        }
        __syncthreads();

        const float2* Ah2 = reinterpret_cast<const float2*>(Ahi);
        const float2* Al2 = reinterpret_cast<const float2*>(Alo);
        const float2* Wh2 = reinterpret_cast<const float2*>(Whi);
        const float2* Wl2 = reinterpret_cast<const float2*>(Wlo);
        int arow = 32 * warp_r + g;
        int brow = 64 * warp_c + g;
#pragma unroll
        for (int kk = 0; kk < 8; kk++) {
            float2 ah0[2], ah1[2], al0[2], al1[2];
#pragma unroll
            for (int mt = 0; mt < 2; mt++) {
                int r = arow + 16 * mt;
                ah0[mt] = Ah2[r * 36 + 4 * kk + t4];
                ah1[mt] = Ah2[(r + 8) * 36 + 4 * kk + t4];
                al0[mt] = Al2[r * 36 + 4 * kk + t4];
                al1[mt] = Al2[(r + 8) * 36 + 4 * kk + t4];
            }
            float2 bh[8], bl[8];
#pragma unroll
            for (int nt = 0; nt < 8; nt++) {
                int n = brow + 8 * nt;
                bh[nt] = Wh2[n * 36 + 4 * kk + t4];
                bl[nt] = Wl2[n * 36 + 4 * kk + t4];
            }
#pragma unroll
            for (int mt = 0; mt < 2; mt++)
#pragma unroll
                for (int nt = 0; nt < 8; nt++) {
                    mma_tf32(acc[mt][nt], ah0[mt].x, ah1[mt].x, ah0[mt].y, ah1[mt].y, bh[nt].x, bh[nt].y);
                    mma_tf32(acc[mt][nt], ah0[mt].x, ah1[mt].x, ah0[mt].y, ah1[mt].y, bl[nt].x, bl[nt].y);
                    mma_tf32(acc[mt][nt], al0[mt].x, al1[mt].x, al0[mt].y, al1[mt].y, bh[nt].x, bh[nt].y);
                }
        }
    }
    __syncthreads();

    float* Ct = psm;
#pragma unroll
    for (int mt = 0; mt < 2; mt++) {
        int row = 32 * warp_r + 16 * mt + g;
#pragma unroll
        for (int nt = 0; nt < 8; nt++) {
            int col = 64 * warp_c + 8 * nt + 2 * t4;
            Ct[row * CT_ROW + col]           = acc[mt][nt][0];
            Ct[row * CT_ROW + col + 1]       = acc[mt][nt][1];
            Ct[(row + 8) * CT_ROW + col]     = acc[mt][nt][2];
            Ct[(row + 8) * CT_ROW + col + 1] = acc[mt][nt][3];
        }
    }
    __syncthreads();

    if (half == 0) {
        for (int i = t; i < 16384; i += 256) {          // n-major, m contiguous -> coalesced
            int n = i >> 7, m = i & 127;
            g_B[p][n][m0 + m] = __float2bfloat16(Ct[m * CT_ROW + n]);
        }
    } else {
        for (int i = t; i < 16384; i += 256) {
            int m = i >> 7, n = i & 127;
            g_S[p][m0 + m][n] = Ct[m * CT_ROW + n];
        }
    }
}

// ===================== main: C = adj_p[m-tile] @ B_p^T, bf16 m16n8k16, KT=64 =================
// grid (64, 2). 8 warps = 4(M) x 2(N), each warp 32 rows x 64 cols (8 n-tiles, symmetric).
// Rowsum: warp_c==0 warps accumulate fp32 A fragments in SIMT during conversion; shfl-reduce
// over t4 at the end (exact fp32 rowsum; no ones-column in B).
// kk-prefetch: fragments for kk+1 loaded while kk's cvt+MMA issue.
__global__ void __launch_bounds__(256, 1) main_kernel(const float* __restrict__ adj_pos,
                                                      const float* __restrict__ adj_neg,
                                                      float* __restrict__ out) {
    extern __shared__ char smc[];
    float* sums = reinterpret_cast<float*>(smc);          // [128]
    uint32_t sb = smem_u32(smc);

    int tid = threadIdx.x;
    int lane = tid & 31, wid = tid >> 5;
    int g = lane >> 2, t4 = lane & 3;
    int warp_r = wid & 3, warp_c = wid >> 2;
    int m0 = blockIdx.x * 128;
    int p = blockIdx.y;
    const float* Ag = p ? adj_neg : adj_pos;
    const __nv_bfloat16* Bg = &g_B[p][0][0];

    auto load_stage = [&](int it, int s) {
        int k0 = it * KT;
        uint32_t abuf = sb + 1024 + (uint32_t)s * STAGE_B;
        uint32_t bbuf = abuf + A_TILE_B;
#pragma unroll
        for (int i = tid; i < 2048; i += 256) {           // A: 128 rows x 16 x 16B (f32)
            int r = i >> 4, c = i & 15;
            CP_ASYNC16(abuf + (uint32_t)(r * AROWB + c * 16),
                       Ag + (size_t)(m0 + r) * N_TOK + k0 + c * 4);
        }
#pragma unroll
        for (int i = tid; i < 1024; i += 256) {           // B: 128 rows x 8 x 16B (bf16)
            int r = i >> 3, c = i & 7;
            CP_ASYNC16(bbuf + (uint32_t)(r * BROWB + c * 16),
                       Bg + (size_t)r * N_TOK + k0 + c * 8);
        }
        CP_COMMIT();
    };

    float acc[2][8][4];
#pragma unroll
    for (int mt = 0; mt < 2; mt++)
#pragma unroll
        for (int nt = 0; nt < 8; nt++)
#pragma unroll
            for (int q = 0; q < 4; q++) acc[mt][nt][q] = 0.f;
    float rsum[2][2] = {{0.f, 0.f}, {0.f, 0.f}};          // [mt][row / row+8]

    int arow = 32 * warp_r + g;
    int brow = 64 * warp_c + g;

    // prologue: 3 stages in flight
    load_stage(0, 0); load_stage(1, 1); load_stage(2, 2);

    for (int it = 0; it < NITER; it++) {
        int s = it - (it / 3) * 3;          // it % 3
        CP_WAITG(2);            // stage `it` complete (it+1, it+2 pending)
        __syncthreads();        // all threads see stage `it`

        const float4* As4 = reinterpret_cast<const float4*>(smc + 1024 + (size_t)s * STAGE_B);
        const uint2* Bw = reinterpret_cast<const uint2*>(smc + 1024 + (size_t)s * STAGE_B + A_TILE_B);

        float4 av[2][4];        // [buf][2*mt + (0:row r, 1:row r+8)]
        uint2  bv[2][8];
#pragma unroll
        for (int mt = 0; mt < 2; mt++) {
            int r = arow + 16 * mt;
            av[0][2 * mt]     = As4[r * 20 + t4];
            av[0][2 * mt + 1] = As4[(r + 8) * 20 + t4];
        }
#pragma unroll
        for (int nt = 0; nt < 8; nt++) bv[0][nt] = Bw[(brow + 8 * nt) * 20 + t4];

#pragma unroll
        for (int kk = 0; kk < 4; kk++) {
            int cur = kk & 1, nxt = cur ^ 1;
            if (kk < 3) {       // prefetch kk+1 fragments
#pragma unroll
                for (int mt = 0; mt < 2; mt++) {
                    int r = arow + 16 * mt;
                    av[nxt][2 * mt]     = As4[r * 20 + 4 * (kk + 1) + t4];
                    av[nxt][2 * mt + 1] = As4[(r + 8) * 20 + 4 * (kk + 1) + t4];
                }
#pragma unroll
                for (int nt = 0; nt < 8; nt++)
                    bv[nxt][nt] = Bw[(brow + 8 * nt) * 20 + 4 * (kk + 1) + t4];
            }
            uint32_t a[2][4];
#pragma unroll
            for (int mt = 0; mt < 2; mt++) {
                float4 v0 = av[cur][2 * mt], v1 = av[cur][2 * mt + 1];
                a[mt][0] = packbf(v0.y, v0.x);
                a[mt][1] = packbf(v1.y, v1.x);
                a[mt][2] = packbf(v0.w, v0.z);
                a[mt][3] = packbf(v1.w, v1.z);
                if (warp_c == 0) {          // fp32 rowsum from the same registers
                    rsum[mt][0] += (v0.x + v0.y) + (v0.z + v0.w);
                    rsum[mt][1] += (v1.x + v1.y) + (v1.z + v1.w);
                }
            }
#pragma unroll
            for (int mt = 0; mt < 2; mt++)
#pragma unroll
                for (int nt = 0; nt < 8; nt++)
                    mma_bf16(acc[mt][nt], a[mt][0], a[mt][1], a[mt][2], a[mt][3],
                             bv[cur][nt].x, bv[cur][nt].y);
        }

        __syncthreads();        // buffer s fully consumed by all warps
        int nit = it + 3;
        if (nit < NITER) load_stage(nit, s);
        else CP_COMMIT();       // keep group count uniform (empty group)
    }

    // ---- rowsum reduce over t4 quads, publish to smem ----
    if (warp_c == 0) {
#pragma unroll
        for (int mt = 0; mt < 2; mt++)
#pragma unroll
            for (int h = 0; h < 2; h++) {
                float v = rsum[mt][h];
                v += __shfl_xor_sync(0xFFFFFFFFu, v, 1);
                v += __shfl_xor_sync(0xFFFFFFFFu, v, 2);
                if (t4 == 0) sums[32 * warp_r + 16 * mt + 8 * h + g] = v;
            }
    }
    __syncthreads();

    // ---- epilogue ----
    int cbase = 64 * warp_c;
#pragma unroll
    for (int mt = 0; mt < 2; mt++) {
        int row = 32 * warp_r + 16 * mt + g;
        float invA = 1.0f / sums[row];
        float invB = 1.0f / sums[row + 8];
        int mA = m0 + row, mB = mA + 8;
        const float* SA = &g_S[p][mA][0];
        const float* SB = &g_S[p][mB][0];
        float* oA = out + (size_t)mA * 256 + p;
        float* oB = out + (size_t)mB * 256 + p;
#pragma unroll
        for (int nt = 0; nt < 8; nt++) {
            int col = cbase + 8 * nt + 2 * t4;
            float2 sA = *reinterpret_cast<const float2*>(SA + col);
            float2 sB = *reinterpret_cast<const float2*>(SB + col);
            oA[(size_t)(col + 0) * 2] = fmaxf(fmaf(acc[mt][nt][0], invA, sA.x), 0.f);
            oA[(size_t)(col + 1) * 2] = fmaxf(fmaf(acc[mt][nt][1], invA, sA.y), 0.f);
            oB[(size_t)(col + 0) * 2] = fmaxf(fmaf(acc[mt][nt][2], invB, sB.x), 0.f);
            oB[(size_t)(col + 1) * 2] = fmaxf(fmaf(acc[mt][nt][3], invB, sB.y), 0.f);
        }
    }
}

// ===================== host =====================
extern "C" void kernel_launch(void* const* d_in, const int* in_sizes, int n_in,
                              void* d_out, int out_size) {
    // metadata order: inputs, adj_pos, adj_neg, h0, WB0, WU0, start, end
    const float* adj_pos = (const float*)d_in[1];
    const float* adj_neg = (const float*)d_in[2];
    const float* h0      = (const float*)d_in[3];
    const float* WB0     = (const float*)d_in[4];
    const float* WU0     = (const float*)d_in[5];
    float* out = (float*)d_out;

    cudaFuncSetAttribute(prep_kernel, cudaFuncAttributeMaxDynamicSharedMemorySize, PREP_SMEM);
    cudaFuncSetAttribute(main_kernel, cudaFuncAttributeMaxDynamicSharedMemorySize, SMEM_MAIN);

    prep_kernel<<<dim3(64, 4), 256, PREP_SMEM>>>(h0, WB0, WU0);
    main_kernel<<<dim3(64, 2), 256, SMEM_MAIN>>>(adj_pos, adj_neg, out);
}